// round 8
// baseline (speedup 1.0000x reference)
#include <cuda_runtime.h>
#include <cuda_bf16.h>

// Problem constants
#define B_ 2
#define T_ 320
#define L_ 207
#define D_ 64
#define S_ 21
#define SL_ 4347
#define SLP_ 4352       // padded attn row stride

#define XN_ ((size_t)B_ * T_ * L_ * D_)   // 8478720

// Scratch (static device globals; no allocation)
__device__ float g_sim[(size_t)B_ * SL_ * L_];                 // [b][s*L+l][m]
__device__ __align__(16) __nv_bfloat16 g_xh[XN_];              // x hi
__device__ __align__(16) __nv_bfloat16 g_xl[XN_];              // x lo
__device__ __align__(16) __nv_bfloat16 g_ah[(size_t)B_ * L_ * SLP_];  // attn hi
__device__ __align__(16) __nv_bfloat16 g_al[(size_t)B_ * L_ * SLP_];  // attn lo

__device__ __forceinline__ int shift_p(int s) { return (s == 0) ? 287 : (21 - s); }

// ---------------- low-level helpers ----------------
__device__ __forceinline__ unsigned sptr(const void* p) {
    unsigned r;
    asm("{.reg .u64 t; cvta.to.shared.u64 t, %1; cvt.u32.u64 %0, t;}" : "=r"(r) : "l"(p));
    return r;
}
__device__ __forceinline__ void ldsm4(unsigned r[4], unsigned a) {
    asm volatile("ldmatrix.sync.aligned.m8n8.x4.shared.b16 {%0,%1,%2,%3},[%4];"
                 : "=r"(r[0]), "=r"(r[1]), "=r"(r[2]), "=r"(r[3]) : "r"(a));
}
__device__ __forceinline__ void ldsm4t(unsigned r[4], unsigned a) {
    asm volatile("ldmatrix.sync.aligned.m8n8.x4.trans.shared.b16 {%0,%1,%2,%3},[%4];"
                 : "=r"(r[0]), "=r"(r[1]), "=r"(r[2]), "=r"(r[3]) : "r"(a));
}
__device__ __forceinline__ void mma16816(float c[4], const unsigned a[4],
                                         unsigned b0, unsigned b1) {
    asm volatile("mma.sync.aligned.m16n8k16.row.col.f32.bf16.bf16.f32 "
                 "{%0,%1,%2,%3},{%4,%5,%6,%7},{%8,%9},{%0,%1,%2,%3};"
                 : "+f"(c[0]), "+f"(c[1]), "+f"(c[2]), "+f"(c[3])
                 : "r"(a[0]), "r"(a[1]), "r"(a[2]), "r"(a[3]), "r"(b0), "r"(b1));
}
__device__ __forceinline__ void cpa(unsigned dst, const void* src, bool v) {
    int sz = v ? 16 : 0;
    asm volatile("cp.async.cg.shared.global [%0], [%1], 16, %2;"
                 :: "r"(dst), "l"(src), "r"(sz));
}
#define CP_COMMIT() asm volatile("cp.async.commit_group;")
#define CP_WAIT1()  asm volatile("cp.async.wait_group 1;")
#define CP_WAIT0()  asm volatile("cp.async.wait_group 0;")

// fp32x4 -> hi/lo bf16x4
__device__ __forceinline__ void cvt4(float4 v, __nv_bfloat16* hp, __nv_bfloat16* lp) {
    __nv_bfloat16 h0 = __float2bfloat16(v.x), h1 = __float2bfloat16(v.y);
    __nv_bfloat16 h2 = __float2bfloat16(v.z), h3 = __float2bfloat16(v.w);
    *(__nv_bfloat162*)(hp)     = __halves2bfloat162(h0, h1);
    *(__nv_bfloat162*)(hp + 2) = __halves2bfloat162(h2, h3);
    *(__nv_bfloat162*)(lp)     = __halves2bfloat162(__float2bfloat16(v.x - __bfloat162float(h0)),
                                                    __float2bfloat16(v.y - __bfloat162float(h1)));
    *(__nv_bfloat162*)(lp + 2) = __halves2bfloat162(__float2bfloat16(v.z - __bfloat162float(h2)),
                                                    __float2bfloat16(v.w - __bfloat162float(h3)));
}

// ---------------------------------------------------------------------------
// Kernel 0: x fp32 -> bf16 hi/lo
// ---------------------------------------------------------------------------
__global__ __launch_bounds__(256) void cvt_x(const float* __restrict__ x) {
    const size_t idx = ((size_t)blockIdx.x * 256 + threadIdx.x) * 4;
    if (idx >= XN_) return;
    cvt4(*(const float4*)(x + idx), g_xh + idx, g_xl + idx);
}

// ---------------------------------------------------------------------------
// Kernel 1: sim GEMM (unchanged from R6 — proven). Block 128(l) x 64(m),
// KC=32, 8 warps, bf16 3-pass MMA, 3-stage ring, single barrier per chunk.
// ---------------------------------------------------------------------------
#define SIM_A 10240
#define SIM_B 5120
#define SIM_STAGE (2 * SIM_A + 2 * SIM_B)   // 30720
#define SIM_SMEM  (3 * SIM_STAGE)           // 92160

__global__ __launch_bounds__(256, 2) void sim_gemm(const float* __restrict__ w) {
    extern __shared__ char sm[];
    const int z = blockIdx.z;
    const int b = z & 1;
    const int s = ((z >> 1) + 1) % S_;
    const int p = shift_p(s);
    const int Tv = T_ - p;
    const int l0 = blockIdx.x * 128, m0 = blockIdx.y * 64;
    const int tid = threadIdx.x, lane = tid & 31, wid = tid >> 5;
    const int wl = (wid & 3) * 32, wm = (wid >> 2) * 32;

    const size_t xoff = (size_t)b * T_ * L_ * D_;
    const __nv_bfloat16* xh = g_xh + xoff;
    const __nv_bfloat16* xl = g_xl + xoff;

    const int rA = lane & 15, cA = lane >> 4;
    const int nB = ((lane >> 4) << 3) + (lane & 7);
    const int kB = ((lane >> 3) & 1) << 3;

    const int arow = tid >> 1, ahalf = tid & 1;
    const int brow = tid >> 2, bq = tid & 3;
    const bool av = (l0 + arow) < L_;
    const bool bv = (m0 + brow) < L_;

    auto ISSUE = [&](int kc, int buf) {
        const int t = kc >> 1, db = (kc & 1) * 32;
        const unsigned sb = sptr(sm + buf * SIM_STAGE);
        const size_t ao = ((size_t)t * L_ + l0 + arow) * D_ + db + ahalf * 16;
        const unsigned ad = sb + arow * 80 + ahalf * 32;
        cpa(ad,              xh + ao,     av);
        cpa(ad + 16,         xh + ao + 8, av);
        cpa(ad + SIM_A,      xl + ao,     av);
        cpa(ad + SIM_A + 16, xl + ao + 8, av);
        const size_t bo = ((size_t)(t + p) * L_ + m0 + brow) * D_ + db + bq * 8;
        const unsigned bd = sb + 2 * SIM_A + brow * 80 + bq * 16;
        cpa(bd,         xh + bo, bv);
        cpa(bd + SIM_B, xl + bo, bv);
    };

    float acc[2][4][4] = {};
    const int nc = Tv * 2;

    ISSUE(0, 0); CP_COMMIT();
    ISSUE(1, 1); CP_COMMIT();

    for (int kc = 0; kc < nc; ++kc) {
        if (kc + 1 < nc) { CP_WAIT1(); } else { CP_WAIT0(); }
        __syncthreads();
        const unsigned base = sptr(sm + (kc % 3) * SIM_STAGE);
#pragma unroll
        for (int s16 = 0; s16 < 2; ++s16) {
            unsigned ah[2][4], al[2][4], bh[2][4], bl[2][4];
#pragma unroll
            for (int mt = 0; mt < 2; ++mt) {
                const unsigned o = base + (wl + mt * 16 + rA) * 80 + (s16 * 16 + cA * 8) * 2;
                ldsm4(ah[mt], o);
                ldsm4(al[mt], o + SIM_A);
            }
#pragma unroll
            for (int g = 0; g < 2; ++g) {
                const unsigned o = base + 2 * SIM_A + (wm + g * 16 + nB) * 80 + (kB + s16 * 16) * 2;
                ldsm4(bh[g], o);
                ldsm4(bl[g], o + SIM_B);
            }
#pragma unroll
            for (int mt = 0; mt < 2; ++mt)
#pragma unroll
                for (int nt = 0; nt < 4; ++nt)
                    mma16816(acc[mt][nt], ah[mt], bh[nt >> 1][(nt & 1) * 2],
                                                  bh[nt >> 1][(nt & 1) * 2 + 1]);
#pragma unroll
            for (int mt = 0; mt < 2; ++mt)
#pragma unroll
                for (int nt = 0; nt < 4; ++nt)
                    mma16816(acc[mt][nt], ah[mt], bl[nt >> 1][(nt & 1) * 2],
                                                  bl[nt >> 1][(nt & 1) * 2 + 1]);
#pragma unroll
            for (int mt = 0; mt < 2; ++mt)
#pragma unroll
                for (int nt = 0; nt < 4; ++nt)
                    mma16816(acc[mt][nt], al[mt], bh[nt >> 1][(nt & 1) * 2],
                                                  bh[nt >> 1][(nt & 1) * 2 + 1]);
        }
        if (kc + 2 < nc) { ISSUE(kc + 2, (kc + 2) % 3); CP_COMMIT(); }
    }

    const float sc = w[0] * (1.f / (float)T_);
    float* C = g_sim + (size_t)b * SL_ * L_ + (size_t)s * L_ * L_;
    const int gg = lane >> 2, tg = (lane & 3) * 2;
#pragma unroll
    for (int mt = 0; mt < 2; ++mt)
#pragma unroll
        for (int nt = 0; nt < 4; ++nt) {
            const int l = l0 + wl + mt * 16 + gg;
            const int m = m0 + wm + nt * 8 + tg;
            const float* a = acc[mt][nt];
            if (l < L_) {
                if (m < L_)     C[(size_t)l * L_ + m]     = a[0] * sc;
                if (m + 1 < L_) C[(size_t)l * L_ + m + 1] = a[1] * sc;
            }
            if (l + 8 < L_) {
                if (m < L_)     C[(size_t)(l + 8) * L_ + m]     = a[2] * sc;
                if (m + 1 < L_) C[(size_t)(l + 8) * L_ + m + 1] = a[3] * sc;
            }
        }
}

// ---------------------------------------------------------------------------
// Kernel 2: softmax over j = s*L+l (stride L_) per (b,m). In place on g_sim.
// ---------------------------------------------------------------------------
__global__ __launch_bounds__(256) void softmax_cols() {
    const int bm = blockIdx.x;
    const int b = bm / L_;
    const int m = bm % L_;
    float* base = g_sim + (size_t)b * SL_ * L_ + m;

    __shared__ float red[256];
    const int tid = threadIdx.x;

    float mx = -1e30f;
    for (int j = tid; j < SL_; j += 256) mx = fmaxf(mx, base[(size_t)j * L_]);
    red[tid] = mx;
    __syncthreads();
    for (int o = 128; o > 0; o >>= 1) {
        if (tid < o) red[tid] = fmaxf(red[tid], red[tid + o]);
        __syncthreads();
    }
    mx = red[0];
    __syncthreads();

    float sum = 0.f;
    for (int j = tid; j < SL_; j += 256) {
        float e = __expf(base[(size_t)j * L_] - mx);
        base[(size_t)j * L_] = e;
        sum += e;
    }
    red[tid] = sum;
    __syncthreads();
    for (int o = 128; o > 0; o >>= 1) {
        if (tid < o) red[tid] += red[tid + o];
        __syncthreads();
    }
    const float inv = 1.f / red[0];
    for (int j = tid; j < SL_; j += 256) base[(size_t)j * L_] *= inv;
}

// ---------------------------------------------------------------------------
// Kernel 3: repack attn view -> padded bf16 hi/lo (g_ah/g_al, stride 4352).
// ---------------------------------------------------------------------------
__global__ __launch_bounds__(256) void repack_attn() {
    const size_t idx = ((size_t)blockIdx.x * 256 + threadIdx.x) * 4;
    if (idx >= (size_t)B_ * L_ * SLP_) return;
    const size_t per = (size_t)L_ * SLP_;
    const int b = (int)(idx / per);
    const size_t rem = idx - (size_t)b * per;
    const int l = (int)(rem / SLP_);
    const int j = (int)(rem - (size_t)l * SLP_);
    const float* src = g_sim + (size_t)b * SL_ * L_ + (size_t)l * SL_ + j;
    float4 v;
    v.x = (j     < SL_) ? src[0] : 0.f;
    v.y = (j + 1 < SL_) ? src[1] : 0.f;
    v.z = (j + 2 < SL_) ? src[2] : 0.f;
    v.w = (j + 3 < SL_) ? src[3] : 0.f;
    cvt4(v, g_ah + idx, g_al + idx);
}

// ---------------------------------------------------------------------------
// Kernel 4: out GEMM, t-pair version. CTA = (l-tile 128, t-pair, b).
// out[b,t0+tn,l,d] = sum_j attn[b,l,j] * x[b, t+p_{j/L}, j%L, d]
// N = 128 (tn x 64 d). 512 threads, 16 warps (warp tile 32 l x 32 n),
// KC=64, 3-stage ring (73728B/stage), single barrier per chunk.
// ---------------------------------------------------------------------------
#define OUT_A 18432                     // 128 rows x 144B (64 bf16 + pad)
#define OUT_B 9216                      // 64 rows x 144B
#define OUT_STAGE (2 * OUT_A + 4 * OUT_B)   // 73728
#define OUT_SMEM  (3 * OUT_STAGE)           // 221184

__global__ __launch_bounds__(512, 1) void out_gemm(float* __restrict__ out) {
    extern __shared__ char sm[];
    const int b = blockIdx.z, t0 = blockIdx.y * 2;
    const int l0 = blockIdx.x * 128;
    const int tid = threadIdx.x, lane = tid & 31, wid = tid >> 5;
    const int wl = (wid & 3) * 32;            // l offset
    const int wn = (wid >> 2) * 32;           // n offset in [0,128)
    const int wtn = wn >> 6;                  // which t of the pair
    const int wd = wn & 63;                   // d offset within t

    const __nv_bfloat16* ah_g = g_ah + (size_t)b * L_ * SLP_;
    const __nv_bfloat16* al_g = g_al + (size_t)b * L_ * SLP_;
    const size_t xoff = (size_t)b * T_ * L_ * D_;
    const __nv_bfloat16* xh = g_xh + xoff;
    const __nv_bfloat16* xl = g_xl + xoff;

    const int rA = lane & 15, cA = lane >> 4;
    const int kBt = (lane & 7) + (((lane >> 3) & 1) << 3);
    const int nBt = (lane >> 4) << 3;

    // loader mapping (512 threads)
    const int ar = tid >> 2, ac = (tid & 3) << 1;   // A: 4 thr/row, 2 segs each
    const int br = tid >> 3, bc = tid & 7;          // B: 8 thr/row (64 rows)
    const bool av = (l0 + ar) < L_;

    auto ISSUE = [&](int kc, int buf) {
        const int j0 = kc * 64;
        const unsigned sb = sptr(sm + buf * OUT_STAGE);
        // A hi/lo: 128 rows x 128B
        const size_t ao = (size_t)(l0 + ar) * SLP_ + j0 + ac * 8;
        const unsigned ad = sb + ar * 144 + ac * 16;
        cpa(ad,              ah_g + ao,     av);
        cpa(ad + 16,         ah_g + ao + 8, av);
        cpa(ad + OUT_A,      al_g + ao,     av);
        cpa(ad + OUT_A + 16, al_g + ao + 8, av);
        // B hi/lo for both t's: 64 rows x 128B each
        const int j = j0 + br;
        const int ss = j / L_;
        const int lk = j - ss * L_;
        const int pb = shift_p(ss);
        const unsigned bd0 = sb + 2 * OUT_A + br * 144 + bc * 16;
#pragma unroll
        for (int tn = 0; tn < 2; ++tn) {
            const int tp = t0 + tn + pb;
            const bool v = (j < SL_) && (tp < T_);
            const size_t bo = ((size_t)tp * L_ + lk) * D_ + bc * 8;
            const unsigned bd = bd0 + tn * (2 * OUT_B);
            cpa(bd,         xh + bo, v);
            cpa(bd + OUT_B, xl + bo, v);
        }
    };

    float acc[2][4][4] = {};
    const int nc = SLP_ / 64;   // 68

    ISSUE(0, 0); CP_COMMIT();
    ISSUE(1, 1); CP_COMMIT();

    for (int kc = 0; kc < nc; ++kc) {
        if (kc + 1 < nc) { CP_WAIT1(); } else { CP_WAIT0(); }
        __syncthreads();
        const unsigned base = sptr(sm + (kc % 3) * OUT_STAGE);
        const unsigned bbase = base + 2 * OUT_A + wtn * (2 * OUT_B);
#pragma unroll
        for (int s16 = 0; s16 < 4; ++s16) {
            unsigned ah[2][4], al[2][4], bh[2][4], bl[2][4];
#pragma unroll
            for (int mt = 0; mt < 2; ++mt) {
                const unsigned o = base + (wl + mt * 16 + rA) * 144 + (s16 * 16 + cA * 8) * 2;
                ldsm4(ah[mt], o);
                ldsm4(al[mt], o + OUT_A);
            }
#pragma unroll
            for (int g = 0; g < 2; ++g) {
                const unsigned o = bbase + (kBt + s16 * 16) * 144 + (wd + g * 16 + nBt) * 2;
                ldsm4t(bh[g], o);
                ldsm4t(bl[g], o + OUT_B);
            }
#pragma unroll
            for (int mt = 0; mt < 2; ++mt)
#pragma unroll
                for (int nt = 0; nt < 4; ++nt)
                    mma16816(acc[mt][nt], ah[mt], bh[nt >> 1][(nt & 1) * 2],
                                                  bh[nt >> 1][(nt & 1) * 2 + 1]);
#pragma unroll
            for (int mt = 0; mt < 2; ++mt)
#pragma unroll
                for (int nt = 0; nt < 4; ++nt)
                    mma16816(acc[mt][nt], ah[mt], bl[nt >> 1][(nt & 1) * 2],
                                                  bl[nt >> 1][(nt & 1) * 2 + 1]);
#pragma unroll
            for (int mt = 0; mt < 2; ++mt)
#pragma unroll
                for (int nt = 0; nt < 4; ++nt)
                    mma16816(acc[mt][nt], al[mt], bh[nt >> 1][(nt & 1) * 2],
                                                  bh[nt >> 1][(nt & 1) * 2 + 1]);
        }
        if (kc + 2 < nc) { ISSUE(kc + 2, (kc + 2) % 3); CP_COMMIT(); }
    }

    float* ob = out + (size_t)(b * T_ + t0 + wtn) * L_ * D_;
    const int gg = lane >> 2, tg = (lane & 3) * 2;
#pragma unroll
    for (int mt = 0; mt < 2; ++mt)
#pragma unroll
        for (int nt = 0; nt < 4; ++nt) {
            const int l = l0 + wl + mt * 16 + gg;
            const int d = wd + nt * 8 + tg;
            const float* a = acc[mt][nt];
            if (l < L_) {
                ob[(size_t)l * D_ + d]     = a[0];
                ob[(size_t)l * D_ + d + 1] = a[1];
            }
            if (l + 8 < L_) {
                ob[(size_t)(l + 8) * D_ + d]     = a[2];
                ob[(size_t)(l + 8) * D_ + d + 1] = a[3];
            }
        }
}

// ---------------------------------------------------------------------------
extern "C" void kernel_launch(void* const* d_in, const int* in_sizes, int n_in,
                              void* d_out, int out_size) {
    const float* x = (const float*)d_in[0];
    const float* w = (const float*)d_in[1];
    float* out = (float*)d_out;

    cudaFuncSetAttribute(sim_gemm, cudaFuncAttributeMaxDynamicSharedMemorySize, SIM_SMEM);
    cudaFuncSetAttribute(out_gemm, cudaFuncAttributeMaxDynamicSharedMemorySize, OUT_SMEM);

    cvt_x<<<(unsigned)((XN_ / 4 + 255) / 256), 256>>>(x);
    sim_gemm<<<dim3(2, 4, B_ * S_), 256, SIM_SMEM>>>(w);
    softmax_cols<<<B_ * L_, 256>>>();
    repack_attn<<<(unsigned)(((size_t)B_ * L_ * SLP_ / 4 + 255) / 256), 256>>>();
    out_gemm<<<dim3(2, T_ / 2, B_), 512, OUT_SMEM>>>(out);
}

// round 9
// speedup vs baseline: 1.1742x; 1.1742x over previous
#include <cuda_runtime.h>
#include <cuda_bf16.h>

// Problem constants
#define B_ 2
#define T_ 320
#define L_ 207
#define D_ 64
#define S_ 21
#define SL_ 4347
#define SLP_ 4352       // padded attn row stride
#define NQ_ 4           // sim K-split factor

#define XN_ ((size_t)B_ * T_ * L_ * D_)   // 8478720
#define SIMSZ_ ((size_t)B_ * SL_ * L_)    // per-quarter sim slice

// Scratch (static device globals; no allocation)
__device__ float g_simQ[NQ_ * SIMSZ_];                         // 4 partial sims
__device__ __align__(16) __nv_bfloat16 g_xh[XN_];              // x hi
__device__ __align__(16) __nv_bfloat16 g_xl[XN_];              // x lo
__device__ __align__(16) __nv_bfloat16 g_ah[(size_t)B_ * L_ * SLP_];  // attn hi
__device__ __align__(16) __nv_bfloat16 g_al[(size_t)B_ * L_ * SLP_];  // attn lo

__device__ __forceinline__ int shift_p(int s) { return (s == 0) ? 287 : (21 - s); }

// ---------------- low-level helpers ----------------
__device__ __forceinline__ unsigned sptr(const void* p) {
    unsigned r;
    asm("{.reg .u64 t; cvta.to.shared.u64 t, %1; cvt.u32.u64 %0, t;}" : "=r"(r) : "l"(p));
    return r;
}
__device__ __forceinline__ void ldsm4(unsigned r[4], unsigned a) {
    asm volatile("ldmatrix.sync.aligned.m8n8.x4.shared.b16 {%0,%1,%2,%3},[%4];"
                 : "=r"(r[0]), "=r"(r[1]), "=r"(r[2]), "=r"(r[3]) : "r"(a));
}
__device__ __forceinline__ void ldsm4t(unsigned r[4], unsigned a) {
    asm volatile("ldmatrix.sync.aligned.m8n8.x4.trans.shared.b16 {%0,%1,%2,%3},[%4];"
                 : "=r"(r[0]), "=r"(r[1]), "=r"(r[2]), "=r"(r[3]) : "r"(a));
}
__device__ __forceinline__ void mma16816(float c[4], const unsigned a[4],
                                         unsigned b0, unsigned b1) {
    asm volatile("mma.sync.aligned.m16n8k16.row.col.f32.bf16.bf16.f32 "
                 "{%0,%1,%2,%3},{%4,%5,%6,%7},{%8,%9},{%0,%1,%2,%3};"
                 : "+f"(c[0]), "+f"(c[1]), "+f"(c[2]), "+f"(c[3])
                 : "r"(a[0]), "r"(a[1]), "r"(a[2]), "r"(a[3]), "r"(b0), "r"(b1));
}
__device__ __forceinline__ void cpa(unsigned dst, const void* src, bool v) {
    int sz = v ? 16 : 0;
    asm volatile("cp.async.cg.shared.global [%0], [%1], 16, %2;"
                 :: "r"(dst), "l"(src), "r"(sz));
}
#define CP_COMMIT() asm volatile("cp.async.commit_group;")
#define CP_WAIT1()  asm volatile("cp.async.wait_group 1;")
#define CP_WAIT0()  asm volatile("cp.async.wait_group 0;")

// fp32x4 -> hi/lo bf16x4
__device__ __forceinline__ void cvt4(float4 v, __nv_bfloat16* hp, __nv_bfloat16* lp) {
    __nv_bfloat16 h0 = __float2bfloat16(v.x), h1 = __float2bfloat16(v.y);
    __nv_bfloat16 h2 = __float2bfloat16(v.z), h3 = __float2bfloat16(v.w);
    *(__nv_bfloat162*)(hp)     = __halves2bfloat162(h0, h1);
    *(__nv_bfloat162*)(hp + 2) = __halves2bfloat162(h2, h3);
    *(__nv_bfloat162*)(lp)     = __halves2bfloat162(__float2bfloat16(v.x - __bfloat162float(h0)),
                                                    __float2bfloat16(v.y - __bfloat162float(h1)));
    *(__nv_bfloat162*)(lp + 2) = __halves2bfloat162(__float2bfloat16(v.z - __bfloat162float(h2)),
                                                    __float2bfloat16(v.w - __bfloat162float(h3)));
}

// ---------------------------------------------------------------------------
// Kernel 0: x fp32 -> bf16 hi/lo
// ---------------------------------------------------------------------------
__global__ __launch_bounds__(256) void cvt_x(const float* __restrict__ x) {
    const size_t idx = ((size_t)blockIdx.x * 256 + threadIdx.x) * 4;
    if (idx >= XN_) return;
    cvt4(*(const float4*)(x + idx), g_xh + idx, g_xl + idx);
}

// ---------------------------------------------------------------------------
// Kernel 1: sim GEMM, 4-way K-split over t. Block 128(l) x 64(m), KC=32,
// 8 warps, bf16 3-pass MMA, 3-stage ring, single barrier per chunk.
// Quarter q covers t in [q*Tv/4, (q+1)*Tv/4), writes partial to g_simQ slice q.
// ---------------------------------------------------------------------------
#define SIM_A 10240
#define SIM_B 5120
#define SIM_STAGE (2 * SIM_A + 2 * SIM_B)   // 30720
#define SIM_SMEM  (3 * SIM_STAGE)           // 92160

__global__ __launch_bounds__(256, 2) void sim_gemm(const float* __restrict__ w) {
    extern __shared__ char sm[];
    const int z = blockIdx.z;
    const int q = z / (B_ * S_);
    const int zz = z - q * (B_ * S_);
    const int b = zz & 1;
    const int s = ((zz >> 1) + 1) % S_;     // s=0 (tiny K) last within each quarter
    const int p = shift_p(s);
    const int Tv = T_ - p;
    const int t0q = (q * Tv) / NQ_;
    const int t1q = ((q + 1) * Tv) / NQ_;
    const int l0 = blockIdx.x * 128, m0 = blockIdx.y * 64;
    const int tid = threadIdx.x, lane = tid & 31, wid = tid >> 5;
    const int wl = (wid & 3) * 32, wm = (wid >> 2) * 32;

    const size_t xoff = (size_t)b * T_ * L_ * D_;
    const __nv_bfloat16* xh = g_xh + xoff;
    const __nv_bfloat16* xl = g_xl + xoff;

    const int rA = lane & 15, cA = lane >> 4;
    const int nB = ((lane >> 4) << 3) + (lane & 7);
    const int kB = ((lane >> 3) & 1) << 3;

    const int arow = tid >> 1, ahalf = tid & 1;
    const int brow = tid >> 2, bq = tid & 3;
    const bool av = (l0 + arow) < L_;
    const bool bv = (m0 + brow) < L_;

    auto ISSUE = [&](int kc, int buf) {
        const int t = t0q + (kc >> 1), db = (kc & 1) * 32;
        const unsigned sb = sptr(sm + buf * SIM_STAGE);
        const size_t ao = ((size_t)t * L_ + l0 + arow) * D_ + db + ahalf * 16;
        const unsigned ad = sb + arow * 80 + ahalf * 32;
        cpa(ad,              xh + ao,     av);
        cpa(ad + 16,         xh + ao + 8, av);
        cpa(ad + SIM_A,      xl + ao,     av);
        cpa(ad + SIM_A + 16, xl + ao + 8, av);
        const size_t bo = ((size_t)(t + p) * L_ + m0 + brow) * D_ + db + bq * 8;
        const unsigned bd = sb + 2 * SIM_A + brow * 80 + bq * 16;
        cpa(bd,         xh + bo, bv);
        cpa(bd + SIM_B, xl + bo, bv);
    };

    float acc[2][4][4] = {};
    const int nc = (t1q - t0q) * 2;

    ISSUE(0, 0); CP_COMMIT();
    ISSUE(1, 1); CP_COMMIT();

    for (int kc = 0; kc < nc; ++kc) {
        if (kc + 1 < nc) { CP_WAIT1(); } else { CP_WAIT0(); }
        __syncthreads();
        const unsigned base = sptr(sm + (kc % 3) * SIM_STAGE);
#pragma unroll
        for (int s16 = 0; s16 < 2; ++s16) {
            unsigned ah[2][4], al[2][4], bh[2][4], bl[2][4];
#pragma unroll
            for (int mt = 0; mt < 2; ++mt) {
                const unsigned o = base + (wl + mt * 16 + rA) * 80 + (s16 * 16 + cA * 8) * 2;
                ldsm4(ah[mt], o);
                ldsm4(al[mt], o + SIM_A);
            }
#pragma unroll
            for (int g = 0; g < 2; ++g) {
                const unsigned o = base + 2 * SIM_A + (wm + g * 16 + nB) * 80 + (kB + s16 * 16) * 2;
                ldsm4(bh[g], o);
                ldsm4(bl[g], o + SIM_B);
            }
#pragma unroll
            for (int mt = 0; mt < 2; ++mt)
#pragma unroll
                for (int nt = 0; nt < 4; ++nt)
                    mma16816(acc[mt][nt], ah[mt], bh[nt >> 1][(nt & 1) * 2],
                                                  bh[nt >> 1][(nt & 1) * 2 + 1]);
#pragma unroll
            for (int mt = 0; mt < 2; ++mt)
#pragma unroll
                for (int nt = 0; nt < 4; ++nt)
                    mma16816(acc[mt][nt], ah[mt], bl[nt >> 1][(nt & 1) * 2],
                                                  bl[nt >> 1][(nt & 1) * 2 + 1]);
#pragma unroll
            for (int mt = 0; mt < 2; ++mt)
#pragma unroll
                for (int nt = 0; nt < 4; ++nt)
                    mma16816(acc[mt][nt], al[mt], bh[nt >> 1][(nt & 1) * 2],
                                                  bh[nt >> 1][(nt & 1) * 2 + 1]);
        }
        if (kc + 2 < nc) { ISSUE(kc + 2, (kc + 2) % 3); CP_COMMIT(); }
    }

    const float sc = w[0] * (1.f / (float)T_);
    float* C = g_simQ + (size_t)q * SIMSZ_ + (size_t)b * SL_ * L_ + (size_t)s * L_ * L_;
    const int gg = lane >> 2, tg = (lane & 3) * 2;
#pragma unroll
    for (int mt = 0; mt < 2; ++mt)
#pragma unroll
        for (int nt = 0; nt < 4; ++nt) {
            const int l = l0 + wl + mt * 16 + gg;
            const int m = m0 + wm + nt * 8 + tg;
            const float* a = acc[mt][nt];
            if (l < L_) {
                if (m < L_)     C[(size_t)l * L_ + m]     = a[0] * sc;
                if (m + 1 < L_) C[(size_t)l * L_ + m + 1] = a[1] * sc;
            }
            if (l + 8 < L_) {
                if (m < L_)     C[(size_t)(l + 8) * L_ + m]     = a[2] * sc;
                if (m + 1 < L_) C[(size_t)(l + 8) * L_ + m + 1] = a[3] * sc;
            }
        }
}

// ---------------------------------------------------------------------------
// Kernel 2: softmax over j = s*L+l (stride L_) per (b,m).
// Pass 1 sums the 4 K-split partials, folds the sum into slice 0, tracks max.
// Passes 2-3 operate in place on slice 0 (same thread owns same j's).
// ---------------------------------------------------------------------------
__global__ __launch_bounds__(256) void softmax_cols() {
    const int bm = blockIdx.x;
    const int b = bm / L_;
    const int m = bm % L_;
    float* base = g_simQ + (size_t)b * SL_ * L_ + m;

    __shared__ float red[256];
    const int tid = threadIdx.x;

    float mx = -1e30f;
    for (int j = tid; j < SL_; j += 256) {
        const size_t o = (size_t)j * L_;
        float v = base[o] + base[SIMSZ_ + o] + base[2 * SIMSZ_ + o] + base[3 * SIMSZ_ + o];
        base[o] = v;
        mx = fmaxf(mx, v);
    }
    red[tid] = mx;
    __syncthreads();
    for (int o = 128; o > 0; o >>= 1) {
        if (tid < o) red[tid] = fmaxf(red[tid], red[tid + o]);
        __syncthreads();
    }
    mx = red[0];
    __syncthreads();

    float sum = 0.f;
    for (int j = tid; j < SL_; j += 256) {
        float e = __expf(base[(size_t)j * L_] - mx);
        base[(size_t)j * L_] = e;
        sum += e;
    }
    red[tid] = sum;
    __syncthreads();
    for (int o = 128; o > 0; o >>= 1) {
        if (tid < o) red[tid] += red[tid + o];
        __syncthreads();
    }
    const float inv = 1.f / red[0];
    for (int j = tid; j < SL_; j += 256) base[(size_t)j * L_] *= inv;
}

// ---------------------------------------------------------------------------
// Kernel 3: repack attn view -> padded bf16 hi/lo (g_ah/g_al, stride 4352).
// attn[b,l,j] = flat g_simQ slice 0 [b][l*SL + j] (reshape is a view).
// ---------------------------------------------------------------------------
__global__ __launch_bounds__(256) void repack_attn() {
    const size_t idx = ((size_t)blockIdx.x * 256 + threadIdx.x) * 4;
    if (idx >= (size_t)B_ * L_ * SLP_) return;
    const size_t per = (size_t)L_ * SLP_;
    const int b = (int)(idx / per);
    const size_t rem = idx - (size_t)b * per;
    const int l = (int)(rem / SLP_);
    const int j = (int)(rem - (size_t)l * SLP_);
    const float* src = g_simQ + (size_t)b * SL_ * L_ + (size_t)l * SL_ + j;
    float4 v;
    v.x = (j     < SL_) ? src[0] : 0.f;
    v.y = (j + 1 < SL_) ? src[1] : 0.f;
    v.z = (j + 2 < SL_) ? src[2] : 0.f;
    v.w = (j + 3 < SL_) ? src[3] : 0.f;
    cvt4(v, g_ah + idx, g_al + idx);
}

// ---------------------------------------------------------------------------
// Kernel 4: out GEMM (exact R6 version — proven fastest).
// Block 128(l) x 64(d) per (b,t), K=4352, KC=32, 8 warps (32x32),
// 3-stage ring, single barrier per chunk.
// ---------------------------------------------------------------------------
#define OUT_A 10240                     // 128 x 80B
#define OUT_B 4608                      // 32 x 144B
#define OUT_STAGE (2 * OUT_A + 2 * OUT_B)   // 29696
#define OUT_SMEM  (3 * OUT_STAGE)           // 89088

__global__ __launch_bounds__(256, 2) void out_gemm(float* __restrict__ out) {
    extern __shared__ char sm[];
    const int z = blockIdx.z;
    const int b = z / T_, t = z % T_;
    const int l0 = blockIdx.x * 128;
    const int tid = threadIdx.x, lane = tid & 31, wid = tid >> 5;
    const int wl = (wid & 3) * 32, wd = (wid >> 2) * 32;

    const __nv_bfloat16* ah_g = g_ah + (size_t)b * L_ * SLP_;
    const __nv_bfloat16* al_g = g_al + (size_t)b * L_ * SLP_;
    const size_t xoff = (size_t)b * T_ * L_ * D_;
    const __nv_bfloat16* xh = g_xh + xoff;
    const __nv_bfloat16* xl = g_xl + xoff;

    const int rA = lane & 15, cA = lane >> 4;
    const int kBt = (lane & 7) + (((lane >> 3) & 1) << 3);
    const int nBt = (lane >> 4) << 3;

    const int arow = tid >> 1, ahalf = tid & 1;
    const int brow = tid >> 3, bseg = tid & 7;
    const bool av = (l0 + arow) < L_;

    auto ISSUE = [&](int kc, int buf) {
        const int j0 = kc * 32;
        const unsigned sb = sptr(sm + buf * OUT_STAGE);
        const size_t ao = (size_t)(l0 + arow) * SLP_ + j0 + ahalf * 16;
        const unsigned ad = sb + arow * 80 + ahalf * 32;
        cpa(ad,              ah_g + ao,     av);
        cpa(ad + 16,         ah_g + ao + 8, av);
        cpa(ad + OUT_A,      al_g + ao,     av);
        cpa(ad + OUT_A + 16, al_g + ao + 8, av);
        const int j = j0 + brow;
        int ss = j / L_;
        int lk = j - ss * L_;
        int tp = t + shift_p(ss);
        const bool bvv = (j < SL_) && (tp < T_);
        const size_t bo = ((size_t)tp * L_ + lk) * D_ + bseg * 8;
        const unsigned bd = sb + 2 * OUT_A + brow * 144 + bseg * 16;
        cpa(bd,         xh + bo, bvv);
        cpa(bd + OUT_B, xl + bo, bvv);
    };

    float acc[2][4][4] = {};
    const int nc = SLP_ / 32;   // 136

    ISSUE(0, 0); CP_COMMIT();
    ISSUE(1, 1); CP_COMMIT();

    for (int kc = 0; kc < nc; ++kc) {
        if (kc + 1 < nc) { CP_WAIT1(); } else { CP_WAIT0(); }
        __syncthreads();
        const unsigned base = sptr(sm + (kc % 3) * OUT_STAGE);
#pragma unroll
        for (int s16 = 0; s16 < 2; ++s16) {
            unsigned ah[2][4], al[2][4], bh[2][4], bl[2][4];
#pragma unroll
            for (int mt = 0; mt < 2; ++mt) {
                const unsigned o = base + (wl + mt * 16 + rA) * 80 + (s16 * 16 + cA * 8) * 2;
                ldsm4(ah[mt], o);
                ldsm4(al[mt], o + OUT_A);
            }
#pragma unroll
            for (int g = 0; g < 2; ++g) {
                const unsigned o = base + 2 * OUT_A +
                                   (kBt + s16 * 16) * 144 + (wd + g * 16 + nBt) * 2;
                ldsm4t(bh[g], o);
                ldsm4t(bl[g], o + OUT_B);
            }
#pragma unroll
            for (int mt = 0; mt < 2; ++mt)
#pragma unroll
                for (int nt = 0; nt < 4; ++nt)
                    mma16816(acc[mt][nt], ah[mt], bh[nt >> 1][(nt & 1) * 2],
                                                  bh[nt >> 1][(nt & 1) * 2 + 1]);
#pragma unroll
            for (int mt = 0; mt < 2; ++mt)
#pragma unroll
                for (int nt = 0; nt < 4; ++nt)
                    mma16816(acc[mt][nt], ah[mt], bl[nt >> 1][(nt & 1) * 2],
                                                  bl[nt >> 1][(nt & 1) * 2 + 1]);
#pragma unroll
            for (int mt = 0; mt < 2; ++mt)
#pragma unroll
                for (int nt = 0; nt < 4; ++nt)
                    mma16816(acc[mt][nt], al[mt], bh[nt >> 1][(nt & 1) * 2],
                                                  bh[nt >> 1][(nt & 1) * 2 + 1]);
        }
        if (kc + 2 < nc) { ISSUE(kc + 2, (kc + 2) % 3); CP_COMMIT(); }
    }

    float* ob = out + (size_t)(b * T_ + t) * L_ * D_;
    const int gg = lane >> 2, tg = (lane & 3) * 2;
#pragma unroll
    for (int mt = 0; mt < 2; ++mt)
#pragma unroll
        for (int nt = 0; nt < 4; ++nt) {
            const int l = l0 + wl + mt * 16 + gg;
            const int d = wd + nt * 8 + tg;
            const float* a = acc[mt][nt];
            if (l < L_) {
                ob[(size_t)l * D_ + d]     = a[0];
                ob[(size_t)l * D_ + d + 1] = a[1];
            }
            if (l + 8 < L_) {
                ob[(size_t)(l + 8) * D_ + d]     = a[2];
                ob[(size_t)(l + 8) * D_ + d + 1] = a[3];
            }
        }
}

// ---------------------------------------------------------------------------
extern "C" void kernel_launch(void* const* d_in, const int* in_sizes, int n_in,
                              void* d_out, int out_size) {
    const float* x = (const float*)d_in[0];
    const float* w = (const float*)d_in[1];
    float* out = (float*)d_out;

    cudaFuncSetAttribute(sim_gemm, cudaFuncAttributeMaxDynamicSharedMemorySize, SIM_SMEM);
    cudaFuncSetAttribute(out_gemm, cudaFuncAttributeMaxDynamicSharedMemorySize, OUT_SMEM);

    cvt_x<<<(unsigned)((XN_ / 4 + 255) / 256), 256>>>(x);
    sim_gemm<<<dim3(2, 4, NQ_ * B_ * S_), 256, SIM_SMEM>>>(w);
    softmax_cols<<<B_ * L_, 256>>>();
    repack_attn<<<(unsigned)(((size_t)B_ * L_ * SLP_ / 4 + 255) / 256), 256>>>();
    out_gemm<<<dim3(2, 1, B_ * T_), 256, OUT_SMEM>>>(out);
}

// round 10
// speedup vs baseline: 1.1801x; 1.0050x over previous
#include <cuda_runtime.h>
#include <cuda_bf16.h>

// Problem constants
#define B_ 2
#define T_ 320
#define L_ 207
#define D_ 64
#define S_ 21
#define SL_ 4347
#define SLP_ 4352       // padded attn row stride
#define NQ_ 6           // sim K-split factor

#define XN_ ((size_t)B_ * T_ * L_ * D_)   // 8478720
#define SIMSZ_ ((size_t)B_ * SL_ * L_)    // per-slice sim size

// Scratch (static device globals; no allocation)
__device__ float g_simQ[NQ_ * SIMSZ_];                         // sim partials
__device__ float g_outp[XN_];                                  // out K-split partial
__device__ __align__(16) __nv_bfloat16 g_xh[XN_];              // x hi
__device__ __align__(16) __nv_bfloat16 g_xl[XN_];              // x lo
__device__ __align__(16) __nv_bfloat16 g_ah[(size_t)B_ * L_ * SLP_];  // attn hi
__device__ __align__(16) __nv_bfloat16 g_al[(size_t)B_ * L_ * SLP_];  // attn lo

__device__ __forceinline__ int shift_p(int s) { return (s == 0) ? 287 : (21 - s); }

// ---------------- low-level helpers ----------------
__device__ __forceinline__ unsigned sptr(const void* p) {
    unsigned r;
    asm("{.reg .u64 t; cvta.to.shared.u64 t, %1; cvt.u32.u64 %0, t;}" : "=r"(r) : "l"(p));
    return r;
}
__device__ __forceinline__ void ldsm4(unsigned r[4], unsigned a) {
    asm volatile("ldmatrix.sync.aligned.m8n8.x4.shared.b16 {%0,%1,%2,%3},[%4];"
                 : "=r"(r[0]), "=r"(r[1]), "=r"(r[2]), "=r"(r[3]) : "r"(a));
}
__device__ __forceinline__ void ldsm4t(unsigned r[4], unsigned a) {
    asm volatile("ldmatrix.sync.aligned.m8n8.x4.trans.shared.b16 {%0,%1,%2,%3},[%4];"
                 : "=r"(r[0]), "=r"(r[1]), "=r"(r[2]), "=r"(r[3]) : "r"(a));
}
__device__ __forceinline__ void mma16816(float c[4], const unsigned a[4],
                                         unsigned b0, unsigned b1) {
    asm volatile("mma.sync.aligned.m16n8k16.row.col.f32.bf16.bf16.f32 "
                 "{%0,%1,%2,%3},{%4,%5,%6,%7},{%8,%9},{%0,%1,%2,%3};"
                 : "+f"(c[0]), "+f"(c[1]), "+f"(c[2]), "+f"(c[3])
                 : "r"(a[0]), "r"(a[1]), "r"(a[2]), "r"(a[3]), "r"(b0), "r"(b1));
}
__device__ __forceinline__ void cpa(unsigned dst, const void* src, bool v) {
    int sz = v ? 16 : 0;
    asm volatile("cp.async.cg.shared.global [%0], [%1], 16, %2;"
                 :: "r"(dst), "l"(src), "r"(sz));
}
#define CP_COMMIT() asm volatile("cp.async.commit_group;")
#define CP_WAIT1()  asm volatile("cp.async.wait_group 1;")
#define CP_WAIT0()  asm volatile("cp.async.wait_group 0;")

// fp32x4 -> hi/lo bf16x4
__device__ __forceinline__ void cvt4(float4 v, __nv_bfloat16* hp, __nv_bfloat16* lp) {
    __nv_bfloat16 h0 = __float2bfloat16(v.x), h1 = __float2bfloat16(v.y);
    __nv_bfloat16 h2 = __float2bfloat16(v.z), h3 = __float2bfloat16(v.w);
    *(__nv_bfloat162*)(hp)     = __halves2bfloat162(h0, h1);
    *(__nv_bfloat162*)(hp + 2) = __halves2bfloat162(h2, h3);
    *(__nv_bfloat162*)(lp)     = __halves2bfloat162(__float2bfloat16(v.x - __bfloat162float(h0)),
                                                    __float2bfloat16(v.y - __bfloat162float(h1)));
    *(__nv_bfloat162*)(lp + 2) = __halves2bfloat162(__float2bfloat16(v.z - __bfloat162float(h2)),
                                                    __float2bfloat16(v.w - __bfloat162float(h3)));
}

// ---------------------------------------------------------------------------
// Kernel 0: x fp32 -> bf16 hi/lo
// ---------------------------------------------------------------------------
__global__ __launch_bounds__(256) void cvt_x(const float* __restrict__ x) {
    const size_t idx = ((size_t)blockIdx.x * 256 + threadIdx.x) * 4;
    if (idx >= XN_) return;
    cvt4(*(const float4*)(x + idx), g_xh + idx, g_xl + idx);
}

// ---------------------------------------------------------------------------
// Kernel 1: sim GEMM, NQ-way K-split over t. Block 128(l) x 64(m), KC=32,
// 8 warps, bf16 3-pass MMA, 3-stage ring, single barrier per chunk.
// ---------------------------------------------------------------------------
#define SIM_A 10240
#define SIM_B 5120
#define SIM_STAGE (2 * SIM_A + 2 * SIM_B)   // 30720
#define SIM_SMEM  (3 * SIM_STAGE)           // 92160

__global__ __launch_bounds__(256, 2) void sim_gemm(const float* __restrict__ w) {
    extern __shared__ char sm[];
    const int z = blockIdx.z;
    const int q = z / (B_ * S_);
    const int zz = z - q * (B_ * S_);
    const int b = zz & 1;
    const int s = ((zz >> 1) + 1) % S_;     // s=0 (tiny K) last within each slice
    const int p = shift_p(s);
    const int Tv = T_ - p;
    const int t0q = (q * Tv) / NQ_;
    const int t1q = ((q + 1) * Tv) / NQ_;
    const int l0 = blockIdx.x * 128, m0 = blockIdx.y * 64;
    const int tid = threadIdx.x, lane = tid & 31, wid = tid >> 5;
    const int wl = (wid & 3) * 32, wm = (wid >> 2) * 32;

    const size_t xoff = (size_t)b * T_ * L_ * D_;
    const __nv_bfloat16* xh = g_xh + xoff;
    const __nv_bfloat16* xl = g_xl + xoff;

    const int rA = lane & 15, cA = lane >> 4;
    const int nB = ((lane >> 4) << 3) + (lane & 7);
    const int kB = ((lane >> 3) & 1) << 3;

    const int arow = tid >> 1, ahalf = tid & 1;
    const int brow = tid >> 2, bq = tid & 3;
    const bool av = (l0 + arow) < L_;
    const bool bv = (m0 + brow) < L_;

    auto ISSUE = [&](int kc, int buf) {
        const int t = t0q + (kc >> 1), db = (kc & 1) * 32;
        const unsigned sb = sptr(sm + buf * SIM_STAGE);
        const size_t ao = ((size_t)t * L_ + l0 + arow) * D_ + db + ahalf * 16;
        const unsigned ad = sb + arow * 80 + ahalf * 32;
        cpa(ad,              xh + ao,     av);
        cpa(ad + 16,         xh + ao + 8, av);
        cpa(ad + SIM_A,      xl + ao,     av);
        cpa(ad + SIM_A + 16, xl + ao + 8, av);
        const size_t bo = ((size_t)(t + p) * L_ + m0 + brow) * D_ + db + bq * 8;
        const unsigned bd = sb + 2 * SIM_A + brow * 80 + bq * 16;
        cpa(bd,         xh + bo, bv);
        cpa(bd + SIM_B, xl + bo, bv);
    };

    float acc[2][4][4] = {};
    const int nc = (t1q - t0q) * 2;

    ISSUE(0, 0); CP_COMMIT();
    ISSUE(1, 1); CP_COMMIT();

    for (int kc = 0; kc < nc; ++kc) {
        if (kc + 1 < nc) { CP_WAIT1(); } else { CP_WAIT0(); }
        __syncthreads();
        const unsigned base = sptr(sm + (kc % 3) * SIM_STAGE);
#pragma unroll
        for (int s16 = 0; s16 < 2; ++s16) {
            unsigned ah[2][4], al[2][4], bh[2][4], bl[2][4];
#pragma unroll
            for (int mt = 0; mt < 2; ++mt) {
                const unsigned o = base + (wl + mt * 16 + rA) * 80 + (s16 * 16 + cA * 8) * 2;
                ldsm4(ah[mt], o);
                ldsm4(al[mt], o + SIM_A);
            }
#pragma unroll
            for (int g = 0; g < 2; ++g) {
                const unsigned o = base + 2 * SIM_A + (wm + g * 16 + nB) * 80 + (kB + s16 * 16) * 2;
                ldsm4(bh[g], o);
                ldsm4(bl[g], o + SIM_B);
            }
#pragma unroll
            for (int mt = 0; mt < 2; ++mt)
#pragma unroll
                for (int nt = 0; nt < 4; ++nt)
                    mma16816(acc[mt][nt], ah[mt], bh[nt >> 1][(nt & 1) * 2],
                                                  bh[nt >> 1][(nt & 1) * 2 + 1]);
#pragma unroll
            for (int mt = 0; mt < 2; ++mt)
#pragma unroll
                for (int nt = 0; nt < 4; ++nt)
                    mma16816(acc[mt][nt], ah[mt], bl[nt >> 1][(nt & 1) * 2],
                                                  bl[nt >> 1][(nt & 1) * 2 + 1]);
#pragma unroll
            for (int mt = 0; mt < 2; ++mt)
#pragma unroll
                for (int nt = 0; nt < 4; ++nt)
                    mma16816(acc[mt][nt], al[mt], bh[nt >> 1][(nt & 1) * 2],
                                                  bh[nt >> 1][(nt & 1) * 2 + 1]);
        }
        if (kc + 2 < nc) { ISSUE(kc + 2, (kc + 2) % 3); CP_COMMIT(); }
    }

    const float sc = w[0] * (1.f / (float)T_);
    float* C = g_simQ + (size_t)q * SIMSZ_ + (size_t)b * SL_ * L_ + (size_t)s * L_ * L_;
    const int gg = lane >> 2, tg = (lane & 3) * 2;
#pragma unroll
    for (int mt = 0; mt < 2; ++mt)
#pragma unroll
        for (int nt = 0; nt < 4; ++nt) {
            const int l = l0 + wl + mt * 16 + gg;
            const int m = m0 + wm + nt * 8 + tg;
            const float* a = acc[mt][nt];
            if (l < L_) {
                if (m < L_)     C[(size_t)l * L_ + m]     = a[0] * sc;
                if (m + 1 < L_) C[(size_t)l * L_ + m + 1] = a[1] * sc;
            }
            if (l + 8 < L_) {
                if (m < L_)     C[(size_t)(l + 8) * L_ + m]     = a[2] * sc;
                if (m + 1 < L_) C[(size_t)(l + 8) * L_ + m + 1] = a[3] * sc;
            }
        }
}

// ---------------------------------------------------------------------------
// Kernel 2: softmax over j = s*L+l (stride L_) per (b,m).
// Pass 1 sums the NQ K-split partials into slice 0, tracks max.
// ---------------------------------------------------------------------------
__global__ __launch_bounds__(256) void softmax_cols() {
    const int bm = blockIdx.x;
    const int b = bm / L_;
    const int m = bm % L_;
    float* base = g_simQ + (size_t)b * SL_ * L_ + m;

    __shared__ float red[256];
    const int tid = threadIdx.x;

    float mx = -1e30f;
    for (int j = tid; j < SL_; j += 256) {
        const size_t o = (size_t)j * L_;
        float v = base[o];
#pragma unroll
        for (int q = 1; q < NQ_; ++q) v += base[q * SIMSZ_ + o];
        base[o] = v;
        mx = fmaxf(mx, v);
    }
    red[tid] = mx;
    __syncthreads();
    for (int o = 128; o > 0; o >>= 1) {
        if (tid < o) red[tid] = fmaxf(red[tid], red[tid + o]);
        __syncthreads();
    }
    mx = red[0];
    __syncthreads();

    float sum = 0.f;
    for (int j = tid; j < SL_; j += 256) {
        float e = __expf(base[(size_t)j * L_] - mx);
        base[(size_t)j * L_] = e;
        sum += e;
    }
    red[tid] = sum;
    __syncthreads();
    for (int o = 128; o > 0; o >>= 1) {
        if (tid < o) red[tid] += red[tid + o];
        __syncthreads();
    }
    const float inv = 1.f / red[0];
    for (int j = tid; j < SL_; j += 256) base[(size_t)j * L_] *= inv;
}

// ---------------------------------------------------------------------------
// Kernel 3: repack attn view -> padded bf16 hi/lo (g_ah/g_al, stride 4352).
// ---------------------------------------------------------------------------
__global__ __launch_bounds__(256) void repack_attn() {
    const size_t idx = ((size_t)blockIdx.x * 256 + threadIdx.x) * 4;
    if (idx >= (size_t)B_ * L_ * SLP_) return;
    const size_t per = (size_t)L_ * SLP_;
    const int b = (int)(idx / per);
    const size_t rem = idx - (size_t)b * per;
    const int l = (int)(rem / SLP_);
    const int j = (int)(rem - (size_t)l * SLP_);
    const float* src = g_simQ + (size_t)b * SL_ * L_ + (size_t)l * SL_ + j;
    float4 v;
    v.x = (j     < SL_) ? src[0] : 0.f;
    v.y = (j + 1 < SL_) ? src[1] : 0.f;
    v.z = (j + 2 < SL_) ? src[2] : 0.f;
    v.w = (j + 3 < SL_) ? src[3] : 0.f;
    cvt4(v, g_ah + idx, g_al + idx);
}

// ---------------------------------------------------------------------------
// Kernel 4: out GEMM, 2-way K-split over j. Block 128(l) x 64(d) per
// (q,b,t); half q covers chunks [q*68,(q+1)*68). q=0 -> out, q=1 -> g_outp.
// KC=32, 8 warps (32x32), 3-stage ring, single barrier per chunk.
// ---------------------------------------------------------------------------
#define OUT_A 10240                     // 128 x 80B
#define OUT_B 4608                      // 32 x 144B
#define OUT_STAGE (2 * OUT_A + 2 * OUT_B)   // 29696
#define OUT_SMEM  (3 * OUT_STAGE)           // 89088

__global__ __launch_bounds__(256, 2) void out_gemm(float* __restrict__ out) {
    extern __shared__ char sm[];
    const int z = blockIdx.z;
    const int q = z / (B_ * T_);
    const int zz = z - q * (B_ * T_);
    const int b = zz / T_, t = zz % T_;
    const int l0 = blockIdx.x * 128;
    const int tid = threadIdx.x, lane = tid & 31, wid = tid >> 5;
    const int wl = (wid & 3) * 32, wd = (wid >> 2) * 32;

    const __nv_bfloat16* ah_g = g_ah + (size_t)b * L_ * SLP_;
    const __nv_bfloat16* al_g = g_al + (size_t)b * L_ * SLP_;
    const size_t xoff = (size_t)b * T_ * L_ * D_;
    const __nv_bfloat16* xh = g_xh + xoff;
    const __nv_bfloat16* xl = g_xl + xoff;

    const int rA = lane & 15, cA = lane >> 4;
    const int kBt = (lane & 7) + (((lane >> 3) & 1) << 3);
    const int nBt = (lane >> 4) << 3;

    const int arow = tid >> 1, ahalf = tid & 1;
    const int brow = tid >> 3, bseg = tid & 7;
    const bool av = (l0 + arow) < L_;

    const int c0 = q * 68;                     // chunk offset for this half

    auto ISSUE = [&](int kc, int buf) {
        const int j0 = (c0 + kc) * 32;
        const unsigned sb = sptr(sm + buf * OUT_STAGE);
        const size_t ao = (size_t)(l0 + arow) * SLP_ + j0 + ahalf * 16;
        const unsigned ad = sb + arow * 80 + ahalf * 32;
        cpa(ad,              ah_g + ao,     av);
        cpa(ad + 16,         ah_g + ao + 8, av);
        cpa(ad + OUT_A,      al_g + ao,     av);
        cpa(ad + OUT_A + 16, al_g + ao + 8, av);
        const int j = j0 + brow;
        int ss = j / L_;
        int lk = j - ss * L_;
        int tp = t + shift_p(ss);
        const bool bvv = (j < SL_) && (tp < T_);
        const size_t bo = ((size_t)tp * L_ + lk) * D_ + bseg * 8;
        const unsigned bd = sb + 2 * OUT_A + brow * 144 + bseg * 16;
        cpa(bd,         xh + bo, bvv);
        cpa(bd + OUT_B, xl + bo, bvv);
    };

    float acc[2][4][4] = {};
    const int nc = 68;

    ISSUE(0, 0); CP_COMMIT();
    ISSUE(1, 1); CP_COMMIT();

    for (int kc = 0; kc < nc; ++kc) {
        if (kc + 1 < nc) { CP_WAIT1(); } else { CP_WAIT0(); }
        __syncthreads();
        const unsigned base = sptr(sm + (kc % 3) * OUT_STAGE);
#pragma unroll
        for (int s16 = 0; s16 < 2; ++s16) {
            unsigned ah[2][4], al[2][4], bh[2][4], bl[2][4];
#pragma unroll
            for (int mt = 0; mt < 2; ++mt) {
                const unsigned o = base + (wl + mt * 16 + rA) * 80 + (s16 * 16 + cA * 8) * 2;
                ldsm4(ah[mt], o);
                ldsm4(al[mt], o + OUT_A);
            }
#pragma unroll
            for (int g = 0; g < 2; ++g) {
                const unsigned o = base + 2 * OUT_A +
                                   (kBt + s16 * 16) * 144 + (wd + g * 16 + nBt) * 2;
                ldsm4t(bh[g], o);
                ldsm4t(bl[g], o + OUT_B);
            }
#pragma unroll
            for (int mt = 0; mt < 2; ++mt)
#pragma unroll
                for (int nt = 0; nt < 4; ++nt)
                    mma16816(acc[mt][nt], ah[mt], bh[nt >> 1][(nt & 1) * 2],
                                                  bh[nt >> 1][(nt & 1) * 2 + 1]);
#pragma unroll
            for (int mt = 0; mt < 2; ++mt)
#pragma unroll
                for (int nt = 0; nt < 4; ++nt)
                    mma16816(acc[mt][nt], ah[mt], bl[nt >> 1][(nt & 1) * 2],
                                                  bl[nt >> 1][(nt & 1) * 2 + 1]);
#pragma unroll
            for (int mt = 0; mt < 2; ++mt)
#pragma unroll
                for (int nt = 0; nt < 4; ++nt)
                    mma16816(acc[mt][nt], al[mt], bh[nt >> 1][(nt & 1) * 2],
                                                  bh[nt >> 1][(nt & 1) * 2 + 1]);
        }
        if (kc + 2 < nc) { ISSUE(kc + 2, (kc + 2) % 3); CP_COMMIT(); }
    }

    float* obase = q ? g_outp : out;
    float* ob = obase + (size_t)(b * T_ + t) * L_ * D_;
    const int gg = lane >> 2, tg = (lane & 3) * 2;
#pragma unroll
    for (int mt = 0; mt < 2; ++mt)
#pragma unroll
        for (int nt = 0; nt < 4; ++nt) {
            const int l = l0 + wl + mt * 16 + gg;
            const int d = wd + nt * 8 + tg;
            const float* a = acc[mt][nt];
            if (l < L_) {
                ob[(size_t)l * D_ + d]     = a[0];
                ob[(size_t)l * D_ + d + 1] = a[1];
            }
            if (l + 8 < L_) {
                ob[(size_t)(l + 8) * D_ + d]     = a[2];
                ob[(size_t)(l + 8) * D_ + d + 1] = a[3];
            }
        }
}

// ---------------------------------------------------------------------------
// Kernel 5: fold the K-split partial into out. out += g_outp.
// ---------------------------------------------------------------------------
__global__ __launch_bounds__(256) void add_out(float* __restrict__ out) {
    const size_t idx = ((size_t)blockIdx.x * 256 + threadIdx.x) * 4;
    if (idx >= XN_) return;
    float4 a = *(const float4*)(out + idx);
    float4 p = *(const float4*)(g_outp + idx);
    a.x += p.x; a.y += p.y; a.z += p.z; a.w += p.w;
    *(float4*)(out + idx) = a;
}

// ---------------------------------------------------------------------------
extern "C" void kernel_launch(void* const* d_in, const int* in_sizes, int n_in,
                              void* d_out, int out_size) {
    const float* x = (const float*)d_in[0];
    const float* w = (const float*)d_in[1];
    float* out = (float*)d_out;

    cudaFuncSetAttribute(sim_gemm, cudaFuncAttributeMaxDynamicSharedMemorySize, SIM_SMEM);
    cudaFuncSetAttribute(out_gemm, cudaFuncAttributeMaxDynamicSharedMemorySize, OUT_SMEM);

    cvt_x<<<(unsigned)((XN_ / 4 + 255) / 256), 256>>>(x);
    sim_gemm<<<dim3(2, 4, NQ_ * B_ * S_), 256, SIM_SMEM>>>(w);
    softmax_cols<<<B_ * L_, 256>>>();
    repack_attn<<<(unsigned)(((size_t)B_ * L_ * SLP_ / 4 + 255) / 256), 256>>>();
    out_gemm<<<dim3(2, 1, 2 * B_ * T_), 256, OUT_SMEM>>>(out);
    add_out<<<(unsigned)((XN_ / 4 + 255) / 256), 256>>>(out);
}